// round 16
// baseline (speedup 1.0000x reference)
#include <cuda_runtime.h>
#include <cuda_fp16.h>
#include <math.h>
#include <stdint.h>

#define T_TOK 8192
#define HDIM 1024
#define FDIM 4096
#define NEXP 8
#define NPAIR (T_TOK * 2)
#define CAPE 3072
#define NROW (NEXP * CAPE)       // 24576
#define NROWA (NROW + 128)
#define ROWTILES (NROW / 128)    // 192

// fp16 GEMM tile geometry: CTA 128x128, 4 warps (64x64), K-chunk 64
#define KCH 64
#define ROWB 144                           // bytes per smem row (128 data + 16 pad)
#define A_TILE_B (128 * ROWB)              // 18432
#define STAGE_B (2 * A_TILE_B)             // 36864
#define NSTAGE 3
#define SM_TILES 1024
#define SM_TOTAL (SM_TILES + NSTAGE * STAGE_B)   // 111616

// prep kernel partition (256 threads/block)
#define W_N4 (NEXP * FDIM * HDIM / 4)      // 8388608 float4
#define PREP_W1_BLK (W_N4 / 2048)          // 4096 (8 float4/thread)
#define PREP_RT_BLK (T_TOK / 8)            // 1024 (warp per token)
#define PREP_IN_BLK ((NROWA + 255) / 256)  // 97
#define PREP_BLOCKS (PREP_W1_BLK + PREP_RT_BLK + PREP_IN_BLK)

// mega gemm grid partition
#define NX1 (FDIM / 128)                   // 32
#define NX2 (HDIM / 128)                   // 8
#define G1_CTAS (NX1 * ROWTILES)           // 6144
#define W2_CONV_BLK (W_N4 / 1024)          // 8192 (128 thr, 8 f4/thr)
#define G2_CTAS (NX2 * ROWTILES)           // 1536
#define MEGA_CTAS (G1_CTAS + W2_CONV_BLK + G2_CTAS)   // 15872

// ---------------- device scratch ----------------
__device__ __half g_W1h[(size_t)NEXP * FDIM * HDIM];
__device__ __half g_W2h[(size_t)NEXP * FDIM * HDIM];
__device__ __half g_Xh [(size_t)T_TOK * HDIM];
__device__ __half g_A1h[(size_t)NROWA * FDIM];
__device__ __half g_Yh [(size_t)NROWA * HDIM];
__device__ int    g_perm[NROWA];
__device__ int    g_idx [NPAIR];
__device__ float  g_wt  [NPAIR];
__device__ int    g_pos [NPAIR];
__device__ int    g_cur [NEXP];
__device__ int    g_band[ROWTILES];
__device__ int    g_conv;

// ---------------- helpers ----------------
__device__ __forceinline__ uint32_t smem_u32(const void* p) {
    return (uint32_t)__cvta_generic_to_shared(p);
}
__device__ __forceinline__ void cp16(uint32_t dst, const void* src) {
    asm volatile("cp.async.cg.shared.global [%0], [%1], 16;"
                 :: "r"(dst), "l"(src) : "memory");
}
#define LDSM4(r0, r1, r2, r3, a) \
    asm volatile("ldmatrix.sync.aligned.m8n8.x4.shared.b16 {%0,%1,%2,%3}, [%4];" \
                 : "=r"(r0), "=r"(r1), "=r"(r2), "=r"(r3) : "r"(a))
__device__ __forceinline__ void mma_f16(float* c, const uint32_t* a,
                                        const uint32_t* b) {
    asm volatile(
        "mma.sync.aligned.m16n8k16.row.col.f32.f16.f16.f32 "
        "{%0,%1,%2,%3}, {%4,%5,%6,%7}, {%8,%9}, {%0,%1,%2,%3};"
        : "+f"(c[0]), "+f"(c[1]), "+f"(c[2]), "+f"(c[3])
        : "r"(a[0]), "r"(a[1]), "r"(a[2]), "r"(a[3]), "r"(b[0]), "r"(b[1]));
}

// ---------------- prep: W1->fp16 | router(+X->fp16) | init ----------------
__global__ __launch_bounds__(256) void prep_kernel(
    const float* __restrict__ X, const float* __restrict__ Wr,
    const float* __restrict__ br, const float4* __restrict__ W1src)
{
    int b = blockIdx.x;
    int tid = threadIdx.x;

    if (b < PREP_W1_BLK) {
        __half2* dst = (__half2*)g_W1h;
#pragma unroll
        for (int j = 0; j < 8; j++) {
            int i = b * 2048 + j * 256 + tid;
            float4 v = W1src[i];
            dst[2 * i + 0] = __floats2half2_rn(v.x, v.y);
            dst[2 * i + 1] = __floats2half2_rn(v.z, v.w);
        }
        return;
    }
    if (b < PREP_W1_BLK + PREP_RT_BLK) {
        int gtid = (b - PREP_W1_BLK) * 256 + tid;
        int t = gtid >> 5;
        int lane = gtid & 31;

        const float* xr = X + (size_t)t * HDIM;
        __half* xh = g_Xh + (size_t)t * HDIM;
        float acc[NEXP];
#pragma unroll
        for (int e = 0; e < NEXP; e++) acc[e] = 0.0f;
        for (int i = lane; i < HDIM; i += 32) {
            float xv = xr[i];
            xh[i] = __float2half_rn(xv);
#pragma unroll
            for (int e = 0; e < NEXP; e++) acc[e] += xv * Wr[e * HDIM + i];
        }
#pragma unroll
        for (int e = 0; e < NEXP; e++) {
#pragma unroll
            for (int o = 16; o > 0; o >>= 1)
                acc[e] += __shfl_down_sync(0xFFFFFFFFu, acc[e], o);
        }
        if (lane == 0) {
            float v[NEXP];
#pragma unroll
            for (int e = 0; e < NEXP; e++) v[e] = acc[e] + br[e];
            int i0 = 0; float v0 = v[0];
#pragma unroll
            for (int e = 1; e < NEXP; e++) if (v[e] > v0) { v0 = v[e]; i0 = e; }
            int i1 = (i0 == 0) ? 1 : 0; float v1 = v[i1];
#pragma unroll
            for (int e = 0; e < NEXP; e++)
                if (e != i0 && v[e] > v1) { v1 = v[e]; i1 = e; }
            float ex = expf(v1 - v0);
            float w0 = 1.0f / (1.0f + ex);
            g_idx[t * 2 + 0] = i0; g_idx[t * 2 + 1] = i1;
            g_wt [t * 2 + 0] = w0; g_wt [t * 2 + 1] = 1.0f - w0;
        }
        return;
    }
    // init segment: perm poison + counters
    int i = (b - PREP_W1_BLK - PREP_RT_BLK) * 256 + tid;
    if (i < NROWA) g_perm[i] = -1;
    if (i < ROWTILES) g_band[i] = 0;
    if (i < NEXP) g_cur[i] = 0;
    if (i == ROWTILES) g_conv = 0;
}

// ---------------- rank: one atomic per pair (order output-invariant) -----
__global__ __launch_bounds__(256) void rank_kernel() {
    int p = blockIdx.x * 256 + threadIdx.x;
    if (p >= NPAIR) return;
    int e = g_idx[p] & (NEXP - 1);
    int r = e * CAPE + atomicAdd(&g_cur[e], 1);
    if (r >= (e + 1) * CAPE) r = (e + 1) * CAPE - 1;   // capacity clamp
    g_pos[p] = r;
    g_perm[r] = p >> 1;
}

// ---------------- GEMM tile body (shared by both GEMMs) ------------------
template<int KDIM, int OUTDIM, bool IS1>
__device__ __forceinline__ void gemm_body(
    const float* __restrict__ bias, int bx, int by, char* smem)
{
    uint32_t sb = smem_u32(smem);
    int tid = threadIdx.x;
    int warp = tid >> 5, lane = tid & 31;
    int g = lane >> 2, t = lane & 3;
    int warp_m = warp & 1, warp_n = warp >> 1;     // 2 x 2 warp grid
    int row0 = by * 128, col0 = bx * 128;

    int* stok = (int*)smem;
    int tk = g_perm[row0 + tid];
    stok[tid] = tk;
    if (!__syncthreads_or(tk >= 0)) return;

    int e = row0 / CAPE;
    const __half* Ah = IS1 ? (const __half*)g_Xh : (const __half*)g_A1h;
    const __half* We = (IS1 ? (const __half*)g_W1h : (const __half*)g_W2h)
                       + (size_t)e * OUTDIM * KDIM;

    const __half* aptr[8];
    const __half* bptr[8];
    uint32_t soff[8];
#pragma unroll
    for (int i = 0; i < 8; i++) {
        int slot = i * 128 + tid;
        int r = slot >> 3, q = slot & 7;
        soff[i] = (uint32_t)(r * ROWB + q * 16);
        if (IS1) {
            int tok = stok[r];
            if (tok < 0) tok = 0;          // pad rows: garbage, never read
            aptr[i] = Ah + (size_t)tok * KDIM + q * 8;
        } else {
            aptr[i] = Ah + (size_t)(row0 + r) * KDIM + q * 8;
        }
        bptr[i] = We + (size_t)(col0 + r) * KDIM + q * 8;
    }

    int ml = lane >> 3, lr = lane & 7;
    uint32_t aoff[4], boff[4];
#pragma unroll
    for (int mi = 0; mi < 4; mi++) {
        int row = warp_m * 64 + mi * 16 + (ml & 1) * 8 + lr;
        aoff[mi] = (uint32_t)(row * ROWB + (ml >> 1) * 16);
    }
#pragma unroll
    for (int nj = 0; nj < 4; nj++) {
        int row = warp_n * 64 + nj * 16 + (ml >> 1) * 8 + lr;
        boff[nj] = (uint32_t)(row * ROWB + (ml & 1) * 16);
    }

    float acc[4][8][4];
#pragma unroll
    for (int mi = 0; mi < 4; mi++)
#pragma unroll
        for (int ni = 0; ni < 8; ni++)
#pragma unroll
            for (int q = 0; q < 4; q++) acc[mi][ni][q] = 0.0f;

    const int NCH = KDIM / KCH;
    uint32_t sbase = sb + SM_TILES;

#pragma unroll
    for (int s = 0; s < 2; s++) {
        uint32_t sA = sbase + s * STAGE_B;
        uint32_t sB = sA + A_TILE_B;
        int kb = s * KCH;
#pragma unroll
        for (int i = 0; i < 8; i++) {
            cp16(sA + soff[i], aptr[i] + kb);
            cp16(sB + soff[i], bptr[i] + kb);
        }
        asm volatile("cp.async.commit_group;" ::: "memory");
    }

    uint32_t afr[2][4][4], bfr[2][8][2];

#pragma unroll 1
    for (int c = 0; c < NCH; c++) {
        asm volatile("cp.async.wait_group 1;" ::: "memory");
        __syncthreads();

        if (c + 2 < NCH) {
            uint32_t sA = sbase + ((c + 2) % NSTAGE) * STAGE_B;
            uint32_t sB = sA + A_TILE_B;
            int kb = (c + 2) * KCH;
#pragma unroll
            for (int i = 0; i < 8; i++) {
                cp16(sA + soff[i], aptr[i] + kb);
                cp16(sB + soff[i], bptr[i] + kb);
            }
        }
        asm volatile("cp.async.commit_group;" ::: "memory");

        uint32_t sA = sbase + (c % NSTAGE) * STAGE_B;
        uint32_t sB = sA + A_TILE_B;

#pragma unroll
        for (int mi = 0; mi < 4; mi++)
            LDSM4(afr[0][mi][0], afr[0][mi][1], afr[0][mi][2], afr[0][mi][3],
                  sA + aoff[mi]);
#pragma unroll
        for (int nj = 0; nj < 4; nj++)
            LDSM4(bfr[0][2 * nj][0], bfr[0][2 * nj][1],
                  bfr[0][2 * nj + 1][0], bfr[0][2 * nj + 1][1],
                  sB + boff[nj]);

#pragma unroll
        for (int ks = 0; ks < 4; ks++) {
            int cur = ks & 1, nxt = cur ^ 1;
            if (ks < 3) {
#pragma unroll
                for (int mi = 0; mi < 4; mi++)
                    LDSM4(afr[nxt][mi][0], afr[nxt][mi][1],
                          afr[nxt][mi][2], afr[nxt][mi][3],
                          sA + aoff[mi] + (ks + 1) * 32);
#pragma unroll
                for (int nj = 0; nj < 4; nj++)
                    LDSM4(bfr[nxt][2 * nj][0], bfr[nxt][2 * nj][1],
                          bfr[nxt][2 * nj + 1][0], bfr[nxt][2 * nj + 1][1],
                          sB + boff[nj] + (ks + 1) * 32);
            }
#pragma unroll
            for (int mi = 0; mi < 4; mi++)
#pragma unroll
                for (int ni = 0; ni < 8; ni++)
                    mma_f16(acc[mi][ni], afr[cur][mi], bfr[cur][ni]);
        }
    }

    // epilogue: bias (+ exact GELU for GEMM1); fp16 stores
    const float* be = bias + (size_t)e * OUTDIM;
    __half* Outh = IS1 ? g_A1h : g_Yh;
#pragma unroll
    for (int mi = 0; mi < 4; mi++) {
        int r = row0 + warp_m * 64 + mi * 16 + g;
#pragma unroll
        for (int ni = 0; ni < 8; ni++) {
            int cc = col0 + warp_n * 64 + ni * 8 + 2 * t;
            float2 bv = *(const float2*)(be + cc);
            float v0 = acc[mi][ni][0] + bv.x;
            float v1 = acc[mi][ni][1] + bv.y;
            float v2 = acc[mi][ni][2] + bv.x;
            float v3 = acc[mi][ni][3] + bv.y;
            if (IS1) {
                v0 = 0.5f * v0 * (1.0f + erff(v0 * 0.70710678118654752f));
                v1 = 0.5f * v1 * (1.0f + erff(v1 * 0.70710678118654752f));
                v2 = 0.5f * v2 * (1.0f + erff(v2 * 0.70710678118654752f));
                v3 = 0.5f * v3 * (1.0f + erff(v3 * 0.70710678118654752f));
            }
            *(__half2*)(Outh + (size_t)r * OUTDIM + cc) =
                __floats2half2_rn(v0, v1);
            *(__half2*)(Outh + (size_t)(r + 8) * OUTDIM + cc) =
                __floats2half2_rn(v2, v3);
        }
    }
}

// ---------------- mega: GEMM1 tiles | W2 conv | GEMM2 tiles (spin-dep) ---
__global__ __launch_bounds__(128, 2) void mega_gemm_kernel(
    const float* __restrict__ b1, const float* __restrict__ b2,
    const float4* __restrict__ W2src)
{
    extern __shared__ char smem[];
    int bid = blockIdx.x;
    int tid = threadIdx.x;

    if (bid < G1_CTAS) {
        int by = bid / NX1;
        gemm_body<HDIM, FDIM, true>(b1, bid % NX1, by, smem);
        __threadfence();
        __syncthreads();
        if (tid == 0) atomicAdd(&g_band[by], 1);
        return;
    }
    if (bid < G1_CTAS + W2_CONV_BLK) {
        // W2 fp32->fp16 conversion (8 float4/thread)
        int cb = bid - G1_CTAS;
        __half2* dst = (__half2*)g_W2h;
#pragma unroll
        for (int j = 0; j < 8; j++) {
            int i = cb * 1024 + j * 128 + tid;
            float4 v = W2src[i];
            dst[2 * i + 0] = __floats2half2_rn(v.x, v.y);
            dst[2 * i + 1] = __floats2half2_rn(v.z, v.w);
        }
        __threadfence();
        __syncthreads();
        if (tid == 0) atomicAdd(&g_conv, 1);
        return;
    }
    // GEMM2 tile: wait for its GEMM1 row band + W2 conversion
    int b2id = bid - G1_CTAS - W2_CONV_BLK;
    int bx = b2id % NX2, by = b2id / NX2;
    if (tid == 0) {
        while (*(volatile int*)&g_band[by] < NX1) __nanosleep(128);
        while (*(volatile int*)&g_conv < W2_CONV_BLK) __nanosleep(128);
    }
    __syncthreads();
    __threadfence();
    gemm_body<FDIM, HDIM, false>(b2, bx, by, smem);
}

// ---------------- finalize: combine + residual + layernorm ----------------
__global__ __launch_bounds__(256) void finalize_kernel(
    const float* __restrict__ X, const float* __restrict__ ln_w,
    const float* __restrict__ ln_b, float* __restrict__ out)
{
    int t = blockIdx.x;
    int tid = threadIdx.x;

    float w0 = g_wt[t * 2 + 0], w1 = g_wt[t * 2 + 1];
    int q0 = g_pos[t * 2 + 0];
    int q1 = g_pos[t * 2 + 1];
    if ((unsigned)q0 >= NROW) q0 = 0;
    if ((unsigned)q1 >= NROW) q1 = 0;
    const uint2* y0 = (const uint2*)(g_Yh + (size_t)q0 * HDIM);
    const uint2* y1 = (const uint2*)(g_Yh + (size_t)q1 * HDIM);
    const float4* xv = (const float4*)(X + (size_t)t * HDIM);

    float4 a = xv[tid];
    uint2 u0 = y0[tid], u1 = y1[tid];
    float2 c0a = __half22float2(*(const __half2*)&u0.x);
    float2 c0b = __half22float2(*(const __half2*)&u0.y);
    float2 c1a = __half22float2(*(const __half2*)&u1.x);
    float2 c1b = __half22float2(*(const __half2*)&u1.y);
    float4 z;
    z.x = a.x + w0 * c0a.x + w1 * c1a.x;
    z.y = a.y + w0 * c0a.y + w1 * c1a.y;
    z.z = a.z + w0 * c0b.x + w1 * c1b.x;
    z.w = a.w + w0 * c0b.y + w1 * c1b.y;
    float s = z.x + z.y + z.z + z.w;
    float sq = z.x * z.x + z.y * z.y + z.z * z.z + z.w * z.w;

#pragma unroll
    for (int o = 16; o > 0; o >>= 1) {
        s  += __shfl_down_sync(0xFFFFFFFFu, s,  o);
        sq += __shfl_down_sync(0xFFFFFFFFu, sq, o);
    }
    __shared__ float rs[8], rq[8];
    int wid = tid >> 5, lane = tid & 31;
    if (lane == 0) { rs[wid] = s; rq[wid] = sq; }
    __syncthreads();
    if (tid == 0) {
        float aa = 0.0f, bb = 0.0f;
#pragma unroll
        for (int w = 0; w < 8; w++) { aa += rs[w]; bb += rq[w]; }
        rs[0] = aa; rq[0] = bb;
    }
    __syncthreads();
    float mu = rs[0] * (1.0f / HDIM);
    float var = rq[0] * (1.0f / HDIM) - mu * mu;
    float rstd = rsqrtf(var + 1e-12f);

    float4 gw = ((const float4*)ln_w)[tid];
    float4 gb = ((const float4*)ln_b)[tid];
    float4 o;
    o.x = (z.x - mu) * rstd * gw.x + gb.x;
    o.y = (z.y - mu) * rstd * gw.y + gb.y;
    o.z = (z.z - mu) * rstd * gw.z + gb.z;
    o.w = (z.w - mu) * rstd * gw.w + gb.w;
    ((float4*)(out + (size_t)t * HDIM))[tid] = o;
}

// ---------------- launch (single stream, no allocations) ----------------
extern "C" void kernel_launch(void* const* d_in, const int* in_sizes, int n_in,
                              void* d_out, int out_size) {
    const float *X = 0, *Wr = 0, *br = 0, *W1 = 0, *b1 = 0, *W2 = 0, *b2 = 0,
                *ln_w = 0, *ln_b = 0;
    for (int i = 0; i < n_in; i++) {
        const float* p = (const float*)d_in[i];
        switch (in_sizes[i]) {
            case T_TOK * HDIM:        if (!X) X = p; break;
            case NEXP * FDIM * HDIM:  if (!W1) W1 = p; else W2 = p; break;
            case NEXP * FDIM:         if (!b1) b1 = p; break;
            case NEXP * HDIM:         if (!Wr) Wr = p; else b2 = p; break;
            case NEXP:                if (!br) br = p; break;
            case HDIM:                if (!ln_w) ln_w = p; else ln_b = p; break;
            default: break;
        }
    }
    if (!X || !Wr || !br || !W1 || !b1 || !W2 || !b2 || !ln_w || !ln_b) {
        X = (const float*)d_in[0]; Wr = (const float*)d_in[1];
        br = (const float*)d_in[2]; W1 = (const float*)d_in[3];
        b1 = (const float*)d_in[4]; W2 = (const float*)d_in[5];
        b2 = (const float*)d_in[6]; ln_w = (const float*)d_in[7];
        ln_b = (const float*)d_in[8];
    }
    float* out = (float*)d_out;

    cudaFuncSetAttribute(mega_gemm_kernel,
                         cudaFuncAttributeMaxDynamicSharedMemorySize, SM_TOTAL);

    prep_kernel<<<PREP_BLOCKS, 256>>>(X, Wr, br, (const float4*)W1);
    rank_kernel<<<NPAIR / 256, 256>>>();
    mega_gemm_kernel<<<MEGA_CTAS, 128, SM_TOTAL>>>(b1, b2, (const float4*)W2);
    finalize_kernel<<<T_TOK, 256>>>(X, ln_w, ln_b, out);
}

// round 17
// speedup vs baseline: 1.0127x; 1.0127x over previous
#include <cuda_runtime.h>
#include <cuda_fp16.h>
#include <math.h>
#include <stdint.h>

#define T_TOK 8192
#define HDIM 1024
#define FDIM 4096
#define NEXP 8
#define NPAIR (T_TOK * 2)
#define CAPE 3072
#define NROW (NEXP * CAPE)       // 24576
#define NROWA (NROW + 128)
#define ROWTILES (NROW / 128)    // 192

// fp16 GEMM tile geometry: CTA 128x128, 4 warps (64x64), K-chunk 64
#define KCH 64
#define ROWB 144                           // bytes per smem row (128 data + 16 pad)
#define A_TILE_B (128 * ROWB)              // 18432
#define STAGE_B (2 * A_TILE_B)             // 36864
#define NSTAGE 3
#define SM_TILES 1024
#define SM_TOTAL (SM_TILES + NSTAGE * STAGE_B)   // 111616

// prep kernel partition (256 threads/block)
#define W_N4 (NEXP * FDIM * HDIM / 4)      // 8388608 float4
#define PREP_W1_BLK (W_N4 / 2048)          // 4096 (8 float4/thread)
#define PREP_RT_BLK (T_TOK / 8)            // 1024 (warp per token)
#define PREP_IN_BLK ((NROWA + 255) / 256)  // 97
#define PREP_BLOCKS (PREP_W1_BLK + PREP_RT_BLK + PREP_IN_BLK)

// gemm1 grid: tiles + trailing W2-conversion blocks (128 thr, 8 f4/thr)
#define NX1 (FDIM / 128)                   // 32
#define NX2 (HDIM / 128)                   // 8
#define G1_CTAS (NX1 * ROWTILES)           // 6144
#define W2_CONV_BLK (W_N4 / 1024)          // 8192

// ---------------- device scratch ----------------
__device__ __half g_W1h[(size_t)NEXP * FDIM * HDIM];
__device__ __half g_W2h[(size_t)NEXP * FDIM * HDIM];
__device__ __half g_Xh [(size_t)T_TOK * HDIM];
__device__ __half g_A1h[(size_t)NROWA * FDIM];
__device__ __half g_Yh [(size_t)NROWA * HDIM];
__device__ int    g_perm[NROWA];
__device__ int    g_idx [NPAIR];
__device__ float  g_wt  [NPAIR];
__device__ int    g_pos [NPAIR];
__device__ int    g_cur [NEXP];

// ---------------- helpers ----------------
__device__ __forceinline__ uint32_t smem_u32(const void* p) {
    return (uint32_t)__cvta_generic_to_shared(p);
}
__device__ __forceinline__ void cp16(uint32_t dst, const void* src) {
    asm volatile("cp.async.cg.shared.global [%0], [%1], 16;"
                 :: "r"(dst), "l"(src) : "memory");
}
#define LDSM4(r0, r1, r2, r3, a) \
    asm volatile("ldmatrix.sync.aligned.m8n8.x4.shared.b16 {%0,%1,%2,%3}, [%4];" \
                 : "=r"(r0), "=r"(r1), "=r"(r2), "=r"(r3) : "r"(a))
__device__ __forceinline__ void mma_f16(float* c, const uint32_t* a,
                                        const uint32_t* b) {
    asm volatile(
        "mma.sync.aligned.m16n8k16.row.col.f32.f16.f16.f32 "
        "{%0,%1,%2,%3}, {%4,%5,%6,%7}, {%8,%9}, {%0,%1,%2,%3};"
        : "+f"(c[0]), "+f"(c[1]), "+f"(c[2]), "+f"(c[3])
        : "r"(a[0]), "r"(a[1]), "r"(a[2]), "r"(a[3]), "r"(b[0]), "r"(b[1]));
}

// ---------------- prep: W1->fp16 | router(+X->fp16) | init ----------------
__global__ __launch_bounds__(256) void prep_kernel(
    const float* __restrict__ X, const float* __restrict__ Wr,
    const float* __restrict__ br, const float4* __restrict__ W1src)
{
    int b = blockIdx.x;
    int tid = threadIdx.x;

    if (b < PREP_W1_BLK) {
        __half2* dst = (__half2*)g_W1h;
#pragma unroll
        for (int j = 0; j < 8; j++) {
            int i = b * 2048 + j * 256 + tid;
            float4 v = W1src[i];
            dst[2 * i + 0] = __floats2half2_rn(v.x, v.y);
            dst[2 * i + 1] = __floats2half2_rn(v.z, v.w);
        }
        return;
    }
    if (b < PREP_W1_BLK + PREP_RT_BLK) {
        int gtid = (b - PREP_W1_BLK) * 256 + tid;
        int t = gtid >> 5;
        int lane = gtid & 31;

        const float* xr = X + (size_t)t * HDIM;
        __half* xh = g_Xh + (size_t)t * HDIM;
        float acc[NEXP];
#pragma unroll
        for (int e = 0; e < NEXP; e++) acc[e] = 0.0f;
        for (int i = lane; i < HDIM; i += 32) {
            float xv = xr[i];
            xh[i] = __float2half_rn(xv);
#pragma unroll
            for (int e = 0; e < NEXP; e++) acc[e] += xv * Wr[e * HDIM + i];
        }
#pragma unroll
        for (int e = 0; e < NEXP; e++) {
#pragma unroll
            for (int o = 16; o > 0; o >>= 1)
                acc[e] += __shfl_down_sync(0xFFFFFFFFu, acc[e], o);
        }
        if (lane == 0) {
            float v[NEXP];
#pragma unroll
            for (int e = 0; e < NEXP; e++) v[e] = acc[e] + br[e];
            int i0 = 0; float v0 = v[0];
#pragma unroll
            for (int e = 1; e < NEXP; e++) if (v[e] > v0) { v0 = v[e]; i0 = e; }
            int i1 = (i0 == 0) ? 1 : 0; float v1 = v[i1];
#pragma unroll
            for (int e = 0; e < NEXP; e++)
                if (e != i0 && v[e] > v1) { v1 = v[e]; i1 = e; }
            float ex = expf(v1 - v0);
            float w0 = 1.0f / (1.0f + ex);
            g_idx[t * 2 + 0] = i0; g_idx[t * 2 + 1] = i1;
            g_wt [t * 2 + 0] = w0; g_wt [t * 2 + 1] = 1.0f - w0;
        }
        return;
    }
    // init segment: perm poison + rank counters
    int i = (b - PREP_W1_BLK - PREP_RT_BLK) * 256 + tid;
    if (i < NROWA) g_perm[i] = -1;
    if (i < NEXP) g_cur[i] = 0;
}

// ---------------- rank: one atomic per pair (order output-invariant) -----
__global__ __launch_bounds__(256) void rank_kernel() {
    int p = blockIdx.x * 256 + threadIdx.x;
    if (p >= NPAIR) return;
    int e = g_idx[p] & (NEXP - 1);
    int r = e * CAPE + atomicAdd(&g_cur[e], 1);
    if (r >= (e + 1) * CAPE) r = (e + 1) * CAPE - 1;   // capacity clamp
    g_pos[p] = r;
    g_perm[r] = p >> 1;
}

// ---------------- fp16 mma GEMM (GEMM1 carries W2 conversion) ------------
// IS1=true : g_A1h = gelu(gather(Xh) @ W1h[e]^T + b1[e]) (fp16 out), K=HDIM
// IS1=false: g_Yh  =        g_A1h   @ W2h[e]^T + b2[e]   (fp16 out), K=FDIM
template<int KDIM, int OUTDIM, bool IS1>
__global__ __launch_bounds__(128, 2) void moe_gemm_kernel(
    const float* __restrict__ bias, const float4* __restrict__ W2src)
{
    constexpr int NX = OUTDIM / 128;
    int bid = blockIdx.x;
    int tid = threadIdx.x;

    if (IS1 && bid >= NX * ROWTILES) {
        // trailing blocks: convert W2 fp32->fp16 (8 float4 per thread)
        int cb = bid - NX * ROWTILES;
        __half2* dst = (__half2*)g_W2h;
#pragma unroll
        for (int j = 0; j < 8; j++) {
            int i = cb * 1024 + j * 128 + tid;
            float4 v = W2src[i];
            dst[2 * i + 0] = __floats2half2_rn(v.x, v.y);
            dst[2 * i + 1] = __floats2half2_rn(v.z, v.w);
        }
        return;
    }

    extern __shared__ char smem[];
    uint32_t sb = smem_u32(smem);
    int warp = tid >> 5, lane = tid & 31;
    int g = lane >> 2, t = lane & 3;
    int warp_m = warp & 1, warp_n = warp >> 1;     // 2 x 2 warp grid
    int bx = bid % NX, by = bid / NX;
    int row0 = by * 128, col0 = bx * 128;

    int* stok = (int*)smem;
    int tk = g_perm[row0 + tid];
    stok[tid] = tk;
    if (!__syncthreads_or(tk >= 0)) return;

    int e = row0 / CAPE;
    const __half* Ah = IS1 ? (const __half*)g_Xh : (const __half*)g_A1h;
    const __half* We = (IS1 ? (const __half*)g_W1h : (const __half*)g_W2h)
                       + (size_t)e * OUTDIM * KDIM;

    const __half* aptr[8];
    const __half* bptr[8];
    uint32_t soff[8];
#pragma unroll
    for (int i = 0; i < 8; i++) {
        int slot = i * 128 + tid;
        int r = slot >> 3, q = slot & 7;
        soff[i] = (uint32_t)(r * ROWB + q * 16);
        if (IS1) {
            int tok = stok[r];
            if (tok < 0) tok = 0;          // pad rows: garbage, never read
            aptr[i] = Ah + (size_t)tok * KDIM + q * 8;
        } else {
            aptr[i] = Ah + (size_t)(row0 + r) * KDIM + q * 8;
        }
        bptr[i] = We + (size_t)(col0 + r) * KDIM + q * 8;
    }

    int ml = lane >> 3, lr = lane & 7;
    uint32_t aoff[4], boff[4];
#pragma unroll
    for (int mi = 0; mi < 4; mi++) {
        int row = warp_m * 64 + mi * 16 + (ml & 1) * 8 + lr;
        aoff[mi] = (uint32_t)(row * ROWB + (ml >> 1) * 16);
    }
#pragma unroll
    for (int nj = 0; nj < 4; nj++) {
        int row = warp_n * 64 + nj * 16 + (ml >> 1) * 8 + lr;
        boff[nj] = (uint32_t)(row * ROWB + (ml & 1) * 16);
    }

    float acc[4][8][4];
#pragma unroll
    for (int mi = 0; mi < 4; mi++)
#pragma unroll
        for (int ni = 0; ni < 8; ni++)
#pragma unroll
            for (int q = 0; q < 4; q++) acc[mi][ni][q] = 0.0f;

    const int NCH = KDIM / KCH;
    uint32_t sbase = sb + SM_TILES;

#pragma unroll
    for (int s = 0; s < 2; s++) {
        uint32_t sA = sbase + s * STAGE_B;
        uint32_t sB = sA + A_TILE_B;
        int kb = s * KCH;
#pragma unroll
        for (int i = 0; i < 8; i++) {
            cp16(sA + soff[i], aptr[i] + kb);
            cp16(sB + soff[i], bptr[i] + kb);
        }
        asm volatile("cp.async.commit_group;" ::: "memory");
    }

    uint32_t afr[2][4][4], bfr[2][8][2];

#pragma unroll 1
    for (int c = 0; c < NCH; c++) {
        asm volatile("cp.async.wait_group 1;" ::: "memory");
        __syncthreads();

        if (c + 2 < NCH) {
            uint32_t sA = sbase + ((c + 2) % NSTAGE) * STAGE_B;
            uint32_t sB = sA + A_TILE_B;
            int kb = (c + 2) * KCH;
#pragma unroll
            for (int i = 0; i < 8; i++) {
                cp16(sA + soff[i], aptr[i] + kb);
                cp16(sB + soff[i], bptr[i] + kb);
            }
        }
        asm volatile("cp.async.commit_group;" ::: "memory");

        uint32_t sA = sbase + (c % NSTAGE) * STAGE_B;
        uint32_t sB = sA + A_TILE_B;

#pragma unroll
        for (int mi = 0; mi < 4; mi++)
            LDSM4(afr[0][mi][0], afr[0][mi][1], afr[0][mi][2], afr[0][mi][3],
                  sA + aoff[mi]);
#pragma unroll
        for (int nj = 0; nj < 4; nj++)
            LDSM4(bfr[0][2 * nj][0], bfr[0][2 * nj][1],
                  bfr[0][2 * nj + 1][0], bfr[0][2 * nj + 1][1],
                  sB + boff[nj]);

#pragma unroll
        for (int ks = 0; ks < 4; ks++) {
            int cur = ks & 1, nxt = cur ^ 1;
            if (ks < 3) {
#pragma unroll
                for (int mi = 0; mi < 4; mi++)
                    LDSM4(afr[nxt][mi][0], afr[nxt][mi][1],
                          afr[nxt][mi][2], afr[nxt][mi][3],
                          sA + aoff[mi] + (ks + 1) * 32);
#pragma unroll
                for (int nj = 0; nj < 4; nj++)
                    LDSM4(bfr[nxt][2 * nj][0], bfr[nxt][2 * nj][1],
                          bfr[nxt][2 * nj + 1][0], bfr[nxt][2 * nj + 1][1],
                          sB + boff[nj] + (ks + 1) * 32);
            }
#pragma unroll
            for (int mi = 0; mi < 4; mi++)
#pragma unroll
                for (int ni = 0; ni < 8; ni++)
                    mma_f16(acc[mi][ni], afr[cur][mi], bfr[cur][ni]);
        }
    }

    // epilogue: bias (+ exact GELU for GEMM1); fp16 stores
    const float* be = bias + (size_t)e * OUTDIM;
    __half* Outh = IS1 ? g_A1h : g_Yh;
#pragma unroll
    for (int mi = 0; mi < 4; mi++) {
        int r = row0 + warp_m * 64 + mi * 16 + g;
#pragma unroll
        for (int ni = 0; ni < 8; ni++) {
            int cc = col0 + warp_n * 64 + ni * 8 + 2 * t;
            float2 bv = *(const float2*)(be + cc);
            float v0 = acc[mi][ni][0] + bv.x;
            float v1 = acc[mi][ni][1] + bv.y;
            float v2 = acc[mi][ni][2] + bv.x;
            float v3 = acc[mi][ni][3] + bv.y;
            if (IS1) {
                v0 = 0.5f * v0 * (1.0f + erff(v0 * 0.70710678118654752f));
                v1 = 0.5f * v1 * (1.0f + erff(v1 * 0.70710678118654752f));
                v2 = 0.5f * v2 * (1.0f + erff(v2 * 0.70710678118654752f));
                v3 = 0.5f * v3 * (1.0f + erff(v3 * 0.70710678118654752f));
            }
            *(__half2*)(Outh + (size_t)r * OUTDIM + cc) =
                __floats2half2_rn(v0, v1);
            *(__half2*)(Outh + (size_t)(r + 8) * OUTDIM + cc) =
                __floats2half2_rn(v2, v3);
        }
    }
}

// ---------------- finalize: combine + residual + layernorm ----------------
__global__ __launch_bounds__(256) void finalize_kernel(
    const float* __restrict__ X, const float* __restrict__ ln_w,
    const float* __restrict__ ln_b, float* __restrict__ out)
{
    int t = blockIdx.x;
    int tid = threadIdx.x;

    float w0 = g_wt[t * 2 + 0], w1 = g_wt[t * 2 + 1];
    int q0 = g_pos[t * 2 + 0];
    int q1 = g_pos[t * 2 + 1];
    if ((unsigned)q0 >= NROW) q0 = 0;
    if ((unsigned)q1 >= NROW) q1 = 0;
    const uint2* y0 = (const uint2*)(g_Yh + (size_t)q0 * HDIM);
    const uint2* y1 = (const uint2*)(g_Yh + (size_t)q1 * HDIM);
    const float4* xv = (const float4*)(X + (size_t)t * HDIM);

    float4 a = xv[tid];
    uint2 u0 = y0[tid], u1 = y1[tid];
    float2 c0a = __half22float2(*(const __half2*)&u0.x);
    float2 c0b = __half22float2(*(const __half2*)&u0.y);
    float2 c1a = __half22float2(*(const __half2*)&u1.x);
    float2 c1b = __half22float2(*(const __half2*)&u1.y);
    float4 z;
    z.x = a.x + w0 * c0a.x + w1 * c1a.x;
    z.y = a.y + w0 * c0a.y + w1 * c1a.y;
    z.z = a.z + w0 * c0b.x + w1 * c1b.x;
    z.w = a.w + w0 * c0b.y + w1 * c1b.y;
    float s = z.x + z.y + z.z + z.w;
    float sq = z.x * z.x + z.y * z.y + z.z * z.z + z.w * z.w;

#pragma unroll
    for (int o = 16; o > 0; o >>= 1) {
        s  += __shfl_down_sync(0xFFFFFFFFu, s,  o);
        sq += __shfl_down_sync(0xFFFFFFFFu, sq, o);
    }
    __shared__ float rs[8], rq[8];
    int wid = tid >> 5, lane = tid & 31;
    if (lane == 0) { rs[wid] = s; rq[wid] = sq; }
    __syncthreads();
    if (tid == 0) {
        float aa = 0.0f, bb = 0.0f;
#pragma unroll
        for (int w = 0; w < 8; w++) { aa += rs[w]; bb += rq[w]; }
        rs[0] = aa; rq[0] = bb;
    }
    __syncthreads();
    float mu = rs[0] * (1.0f / HDIM);
    float var = rq[0] * (1.0f / HDIM) - mu * mu;
    float rstd = rsqrtf(var + 1e-12f);

    float4 gw = ((const float4*)ln_w)[tid];
    float4 gb = ((const float4*)ln_b)[tid];
    float4 o;
    o.x = (z.x - mu) * rstd * gw.x + gb.x;
    o.y = (z.y - mu) * rstd * gw.y + gb.y;
    o.z = (z.z - mu) * rstd * gw.z + gb.z;
    o.w = (z.w - mu) * rstd * gw.w + gb.w;
    ((float4*)(out + (size_t)t * HDIM))[tid] = o;
}

// ---------------- launch (single stream, no allocations) ----------------
extern "C" void kernel_launch(void* const* d_in, const int* in_sizes, int n_in,
                              void* d_out, int out_size) {
    const float *X = 0, *Wr = 0, *br = 0, *W1 = 0, *b1 = 0, *W2 = 0, *b2 = 0,
                *ln_w = 0, *ln_b = 0;
    for (int i = 0; i < n_in; i++) {
        const float* p = (const float*)d_in[i];
        switch (in_sizes[i]) {
            case T_TOK * HDIM:        if (!X) X = p; break;
            case NEXP * FDIM * HDIM:  if (!W1) W1 = p; else W2 = p; break;
            case NEXP * FDIM:         if (!b1) b1 = p; break;
            case NEXP * HDIM:         if (!Wr) Wr = p; else b2 = p; break;
            case NEXP:                if (!br) br = p; break;
            case HDIM:                if (!ln_w) ln_w = p; else ln_b = p; break;
            default: break;
        }
    }
    if (!X || !Wr || !br || !W1 || !b1 || !W2 || !b2 || !ln_w || !ln_b) {
        X = (const float*)d_in[0]; Wr = (const float*)d_in[1];
        br = (const float*)d_in[2]; W1 = (const float*)d_in[3];
        b1 = (const float*)d_in[4]; W2 = (const float*)d_in[5];
        b2 = (const float*)d_in[6]; ln_w = (const float*)d_in[7];
        ln_b = (const float*)d_in[8];
    }
    float* out = (float*)d_out;

    cudaFuncSetAttribute(moe_gemm_kernel<HDIM, FDIM, true>,
                         cudaFuncAttributeMaxDynamicSharedMemorySize, SM_TOTAL);
    cudaFuncSetAttribute(moe_gemm_kernel<FDIM, HDIM, false>,
                         cudaFuncAttributeMaxDynamicSharedMemorySize, SM_TOTAL);

    prep_kernel<<<PREP_BLOCKS, 256>>>(X, Wr, br, (const float4*)W1);
    rank_kernel<<<NPAIR / 256, 256>>>();
    moe_gemm_kernel<HDIM, FDIM, true>
        <<<G1_CTAS + W2_CONV_BLK, 128, SM_TOTAL>>>(b1, (const float4*)W2);
    moe_gemm_kernel<FDIM, HDIM, false>
        <<<NX2 * ROWTILES, 128, SM_TOTAL>>>(b2, nullptr);
    finalize_kernel<<<T_TOK, 256>>>(X, ln_w, ln_b, out);
}